// round 4
// baseline (speedup 1.0000x reference)
#include <cuda_runtime.h>
#include <cstdint>
#include <cstddef>

// Problem constants
#define BB 4
#define SS 1024
#define DD 1024
#define HH 16
#define HDIM 64

// Scratch: q/k/v in [B, H, S, HD] layout. 3 x 16MB. __device__ globals (no alloc).
__device__ float g_q[(size_t)BB * HH * SS * HDIM];
__device__ float g_k[(size_t)BB * HH * SS * HDIM];
__device__ float g_v[(size_t)BB * HH * SS * HDIM];

// ---------------------------------------------------------------------------
// Kernel 1: QKV projection.  C[M=4096, N=3072] = x[4096,1024] @ W[1024,3072] + b
// Epilogue scatters into g_q/g_k/g_v with the [B,H,S,HD] transpose fused in.
// Tile 64x64, K-chunk 32, 256 threads, 4x4 microtile per thread.
// ---------------------------------------------------------------------------
__global__ __launch_bounds__(256) void qkv_gemm_kernel(
    const float* __restrict__ x,
    const float* __restrict__ W,
    const float* __restrict__ bias)
{
    __shared__ float As[32][68];   // [k][m], pad keeps float4 alignment
    __shared__ float Bs[32][68];   // [k][n]

    const int tid = threadIdx.x;
    const int m0 = blockIdx.y * 64;
    const int n0 = blockIdx.x * 64;
    const int tx = tid & 15;
    const int ty = tid >> 4;
    const int mr = ty * 4;
    const int nc = tx * 4;

    float acc[4][4];
#pragma unroll
    for (int i = 0; i < 4; i++)
#pragma unroll
        for (int j = 0; j < 4; j++) acc[i][j] = 0.0f;

    for (int k0 = 0; k0 < 1024; k0 += 32) {
#pragma unroll
        for (int it = 0; it < 2; it++) {
            int idx = tid + it * 256;                  // 0..511
            // A: 64 rows x 8 float4
            int arow = idx >> 3;
            int akq  = (idx & 7) * 4;
            float4 va = *(const float4*)&x[(size_t)(m0 + arow) * 1024 + k0 + akq];
            As[akq + 0][arow] = va.x;
            As[akq + 1][arow] = va.y;
            As[akq + 2][arow] = va.z;
            As[akq + 3][arow] = va.w;
            // B: 32 rows x 16 float4
            int bkk = idx >> 4;
            int bnq = (idx & 15) * 4;
            *(float4*)&Bs[bkk][bnq] =
                *(const float4*)&W[(size_t)(k0 + bkk) * 3072 + n0 + bnq];
        }
        __syncthreads();

#pragma unroll
        for (int kk = 0; kk < 32; kk++) {
            float4 a4 = *(const float4*)&As[kk][mr];
            float4 b4 = *(const float4*)&Bs[kk][nc];
            float av[4] = {a4.x, a4.y, a4.z, a4.w};
            float bv[4] = {b4.x, b4.y, b4.z, b4.w};
#pragma unroll
            for (int i = 0; i < 4; i++)
#pragma unroll
                for (int j = 0; j < 4; j++)
                    acc[i][j] = fmaf(av[i], bv[j], acc[i][j]);
        }
        __syncthreads();
    }

    // Epilogue: bias + scatter. Column n -> head h = n/192, r = n%192:
    // r in [0,64) -> q, [64,128) -> k, [128,192) -> v; hd = r % 64.
#pragma unroll
    for (int j = 0; j < 4; j++) {
        int n = n0 + nc + j;
        float bn = __ldg(&bias[n]);
        int h = n / 192;
        int r = n - h * 192;
        int sel = r >> 6;          // 0,1,2
        int hd = r & 63;
        float* dst = (sel == 0) ? g_q : (sel == 1) ? g_k : g_v;
#pragma unroll
        for (int i = 0; i < 4; i++) {
            int m = m0 + mr + i;
            int bidx = m >> 10;
            int s = m & 1023;
            dst[((((size_t)bidx * HH + h) << 10) + s) * HDIM + hd] = acc[i][j] + bn;
        }
    }
}

// ---------------------------------------------------------------------------
// Kernel 2: flash attention, fp32, online softmax.
// One CTA per (q_tile of 64, h, b). 256 threads: 16x16 grid, 4 queries x 4
// keys (QK phase) / 4 queries x 4 dims (PV phase) microtiles.
// Dynamic smem: Qt[64][68] (d-major), Kt[64][68] (d-major), Vs[64][68],
// Ps[64][68] = 69632 bytes.
// ---------------------------------------------------------------------------
#define ATTN_SMEM_BYTES (4 * 64 * 68 * 4)

__global__ __launch_bounds__(256) void attn_kernel(float* __restrict__ out)
{
    extern __shared__ float smem[];
    float (*Qt)[68] = (float(*)[68])(smem);                 // [d][query]
    float (*Kt)[68] = (float(*)[68])(smem + 64 * 68);       // [d][key]
    float (*Vs)[68] = (float(*)[68])(smem + 2 * 64 * 68);   // [key][d]
    float (*Ps)[68] = (float(*)[68])(smem + 3 * 64 * 68);   // [query][key]

    const int qt = blockIdx.x;
    const int h  = blockIdx.y;
    const int b  = blockIdx.z;

    const size_t head_off = (((size_t)b * HH + h) << 10) * HDIM;
    const float* qp    = g_q + head_off + (size_t)qt * 64 * HDIM;
    const float* kbase = g_k + head_off;
    const float* vbase = g_v + head_off;

    const int tid = threadIdx.x;
    const int tx = tid & 15;
    const int g  = tid >> 4;
    const int qr = g * 4;
    const int cc = tx * 4;

    // Load Q tile, transposed to [d][query]
#pragma unroll
    for (int it = 0; it < 4; it++) {
        int idx = tid + it * 256;      // 0..1023 float4s
        int row = idx >> 4;            // query
        int col = (idx & 15) * 4;      // d
        float4 va = *(const float4*)&qp[row * HDIM + col];
        Qt[col + 0][row] = va.x;
        Qt[col + 1][row] = va.y;
        Qt[col + 2][row] = va.z;
        Qt[col + 3][row] = va.w;
    }

    float m_i[4], l_i[4], o[4][4];
#pragma unroll
    for (int i = 0; i < 4; i++) {
        m_i[i] = -1e30f;
        l_i[i] = 0.0f;
#pragma unroll
        for (int j = 0; j < 4; j++) o[i][j] = 0.0f;
    }

    for (int kt = 0; kt < 16; kt++) {
        const float* kp = kbase + (size_t)kt * 64 * HDIM;
        const float* vp = vbase + (size_t)kt * 64 * HDIM;

        __syncthreads();   // previous iter's PV done (and first iter: Qt loaded)
#pragma unroll
        for (int it = 0; it < 4; it++) {
            int idx = tid + it * 256;
            int row = idx >> 4;
            int col = (idx & 15) * 4;
            float4 vk = *(const float4*)&kp[row * HDIM + col];
            Kt[col + 0][row] = vk.x;
            Kt[col + 1][row] = vk.y;
            Kt[col + 2][row] = vk.z;
            Kt[col + 3][row] = vk.w;
            *(float4*)&Vs[row][col] = *(const float4*)&vp[row * HDIM + col];
        }
        __syncthreads();

        // S = (Q K^T) * 1/8 for this tile: 4 queries x 4 keys per thread
        float s[4][4];
#pragma unroll
        for (int i = 0; i < 4; i++)
#pragma unroll
            for (int j = 0; j < 4; j++) s[i][j] = 0.0f;

#pragma unroll 16
        for (int d = 0; d < 64; d++) {
            float4 a4 = *(const float4*)&Qt[d][qr];
            float4 k4 = *(const float4*)&Kt[d][cc];
            float av[4] = {a4.x, a4.y, a4.z, a4.w};
            float kv[4] = {k4.x, k4.y, k4.z, k4.w};
#pragma unroll
            for (int i = 0; i < 4; i++)
#pragma unroll
                for (int j = 0; j < 4; j++)
                    s[i][j] = fmaf(av[i], kv[j], s[i][j]);
        }
#pragma unroll
        for (int i = 0; i < 4; i++)
#pragma unroll
            for (int j = 0; j < 4; j++) s[i][j] *= 0.125f;

        // Online softmax update. Row groups = 16 contiguous lanes (xor 1..8 ok).
#pragma unroll
        for (int i = 0; i < 4; i++) {
            float t = fmaxf(fmaxf(s[i][0], s[i][1]), fmaxf(s[i][2], s[i][3]));
            t = fmaxf(t, __shfl_xor_sync(0xffffffffu, t, 8));
            t = fmaxf(t, __shfl_xor_sync(0xffffffffu, t, 4));
            t = fmaxf(t, __shfl_xor_sync(0xffffffffu, t, 2));
            t = fmaxf(t, __shfl_xor_sync(0xffffffffu, t, 1));

            float mnew = fmaxf(m_i[i], t);
            float corr = __expf(m_i[i] - mnew);
            m_i[i] = mnew;

            float ps = 0.0f;
#pragma unroll
            for (int j = 0; j < 4; j++) {
                float p = __expf(s[i][j] - mnew);
                s[i][j] = p;
                ps += p;
            }
            ps += __shfl_xor_sync(0xffffffffu, ps, 8);
            ps += __shfl_xor_sync(0xffffffffu, ps, 4);
            ps += __shfl_xor_sync(0xffffffffu, ps, 2);
            ps += __shfl_xor_sync(0xffffffffu, ps, 1);

            l_i[i] = l_i[i] * corr + ps;
#pragma unroll
            for (int j = 0; j < 4; j++) o[i][j] *= corr;
        }

        // Store P tile
#pragma unroll
        for (int i = 0; i < 4; i++)
            *(float4*)&Ps[qr + i][cc] =
                make_float4(s[i][0], s[i][1], s[i][2], s[i][3]);
        __syncthreads();

        // O += P @ V : per thread, 4 queries x 4 dims (dims = cc..cc+3)
#pragma unroll 16
        for (int j = 0; j < 64; j++) {
            float4 v4 = *(const float4*)&Vs[j][cc];
            float vv[4] = {v4.x, v4.y, v4.z, v4.w};
            float p0 = Ps[qr + 0][j];
            float p1 = Ps[qr + 1][j];
            float p2 = Ps[qr + 2][j];
            float p3 = Ps[qr + 3][j];
#pragma unroll
            for (int jd = 0; jd < 4; jd++) {
                o[0][jd] = fmaf(p0, vv[jd], o[0][jd]);
                o[1][jd] = fmaf(p1, vv[jd], o[1][jd]);
                o[2][jd] = fmaf(p2, vv[jd], o[2][jd]);
                o[3][jd] = fmaf(p3, vv[jd], o[3][jd]);
            }
        }
    }

    // Normalize + write: out[b][s][h*64 + d]
#pragma unroll
    for (int i = 0; i < 4; i++) {
        float inv = 1.0f / l_i[i];
        int srow = qt * 64 + qr + i;
        float4 r = make_float4(o[i][0] * inv, o[i][1] * inv,
                               o[i][2] * inv, o[i][3] * inv);
        *(float4*)&out[((((size_t)b << 10) + srow) << 10) + h * HDIM + cc] = r;
    }
}

// ---------------------------------------------------------------------------
extern "C" void kernel_launch(void* const* d_in, const int* in_sizes, int n_in,
                              void* d_out, int out_size)
{
    (void)in_sizes; (void)n_in; (void)out_size;
    const float* x    = (const float*)d_in[0];
    const float* W    = (const float*)d_in[1];
    const float* bias = (const float*)d_in[2];
    float* out = (float*)d_out;

    cudaFuncSetAttribute(attn_kernel,
                         cudaFuncAttributeMaxDynamicSharedMemorySize,
                         ATTN_SMEM_BYTES);

    dim3 ggrid(3072 / 64, 4096 / 64);   // (48, 64)
    qkv_gemm_kernel<<<ggrid, 256>>>(x, W, bias);

    dim3 agrid(SS / 64, HH, BB);        // (16, 16, 4)
    attn_kernel<<<agrid, 256, ATTN_SMEM_BYTES>>>(out);
}

// round 6
// speedup vs baseline: 1.6171x; 1.6171x over previous
#include <cuda_runtime.h>
#include <cuda_bf16.h>
#include <cstdint>
#include <cstddef>

// Problem constants
#define BB 4
#define SS 1024
#define DD 1024
#define HH 16
#define HDIM 64

// Scratch (no alloc allowed): q/k/v in [B,H,S,HD] fp32, + bf16 hi/lo operands
__device__ float g_q[(size_t)BB * HH * SS * HDIM];
__device__ float g_k[(size_t)BB * HH * SS * HDIM];
__device__ float g_v[(size_t)BB * HH * SS * HDIM];
__device__ __nv_bfloat16 g_Ah[(size_t)4096 * 1024];
__device__ __nv_bfloat16 g_Al[(size_t)4096 * 1024];
__device__ __nv_bfloat16 g_Bh[(size_t)3072 * 1024];   // W transposed: [n][k]
__device__ __nv_bfloat16 g_Bl[(size_t)3072 * 1024];

// ---------------------------------------------------------------------------
// Portable (compute_103-legal) tensor-core PTX: mma.sync + ldmatrix + cp.async
// ---------------------------------------------------------------------------
__device__ __forceinline__ uint32_t smem_to_u32(const void* p) {
    uint32_t a;
    asm("{ .reg .u64 t; cvta.to.shared.u64 t, %1; cvt.u32.u64 %0, t; }"
        : "=r"(a) : "l"(p));
    return a;
}

#define CP_ASYNC16(dst_u32, src_ptr) \
    asm volatile("cp.async.cg.shared.global [%0], [%1], 16;" \
        :: "r"(dst_u32), "l"(src_ptr) : "memory")
#define CP_ASYNC_COMMIT() asm volatile("cp.async.commit_group;" ::: "memory")
#define CP_ASYNC_WAIT_ALL() asm volatile("cp.async.wait_group 0;" ::: "memory")

#define LDSM_X4(r0, r1, r2, r3, addr) \
    asm volatile("ldmatrix.sync.aligned.m8n8.x4.shared.b16 {%0,%1,%2,%3}, [%4];" \
        : "=r"(r0), "=r"(r1), "=r"(r2), "=r"(r3) : "r"(addr))

#define MMA_BF16(d, a, b) \
    asm volatile("mma.sync.aligned.m16n8k16.row.col.f32.bf16.bf16.f32 " \
        "{%0,%1,%2,%3}, {%4,%5,%6,%7}, {%8,%9}, {%0,%1,%2,%3};" \
        : "+f"((d)[0]), "+f"((d)[1]), "+f"((d)[2]), "+f"((d)[3]) \
        : "r"((a)[0]), "r"((a)[1]), "r"((a)[2]), "r"((a)[3]), \
          "r"((b)[0]), "r"((b)[1]))

// ---------------------------------------------------------------------------
// Prep kernel 1: x [4096,1024] fp32 -> Ah/Al bf16 hi/lo
// ---------------------------------------------------------------------------
__global__ __launch_bounds__(256) void prep_x_kernel(
    const float* __restrict__ x,
    __nv_bfloat16* __restrict__ Ah, __nv_bfloat16* __restrict__ Al)
{
    size_t i = ((size_t)blockIdx.x * 256 + threadIdx.x) * 4;
    float4 v = *(const float4*)(x + i);
    float vv[4] = {v.x, v.y, v.z, v.w};
    __nv_bfloat16 h[4], l[4];
#pragma unroll
    for (int j = 0; j < 4; j++) {
        h[j] = __float2bfloat16(vv[j]);
        l[j] = __float2bfloat16(vv[j] - __bfloat162float(h[j]));
    }
    *(__nv_bfloat162*)(Ah + i)     = __nv_bfloat162{h[0], h[1]};
    *(__nv_bfloat162*)(Ah + i + 2) = __nv_bfloat162{h[2], h[3]};
    *(__nv_bfloat162*)(Al + i)     = __nv_bfloat162{l[0], l[1]};
    *(__nv_bfloat162*)(Al + i + 2) = __nv_bfloat162{l[2], l[3]};
}

// ---------------------------------------------------------------------------
// Prep kernel 2: W [1024,3072] fp32 -> transposed Bh/Bl [3072,1024] bf16
// ---------------------------------------------------------------------------
__global__ __launch_bounds__(256) void prep_w_kernel(
    const float* __restrict__ W,
    __nv_bfloat16* __restrict__ Bh, __nv_bfloat16* __restrict__ Bl)
{
    __shared__ float t[32][33];
    int n0 = blockIdx.x * 32, k0 = blockIdx.y * 32;
    int tx = threadIdx.x & 31, ty = threadIdx.x >> 5;    // ty 0..7
#pragma unroll
    for (int i = 0; i < 4; i++) {
        int k = k0 + ty + i * 8;
        t[ty + i * 8][tx] = W[(size_t)k * 3072 + n0 + tx];
    }
    __syncthreads();
#pragma unroll
    for (int i = 0; i < 4; i++) {
        int n = n0 + ty + i * 8;
        float v = t[tx][ty + i * 8];
        __nv_bfloat16 h = __float2bfloat16(v);
        Bh[(size_t)n * 1024 + k0 + tx] = h;
        Bl[(size_t)n * 1024 + k0 + tx] = __float2bfloat16(v - __bfloat162float(h));
    }
}

// ---------------------------------------------------------------------------
// QKV GEMM on HMMA (mma.sync bf16, fp32 accum, hi/lo 3-pass split).
// C[4096,3072] = x @ W + b.  CTA tile 128x128, BK=32, 8 warps @ 64x32,
// cp.async double-buffered smem.  Epilogue: bias + [B,H,S,HD] scatter.
// ---------------------------------------------------------------------------
#define GBM 128
#define GBN 128
#define GBK 32
#define LDA 40                       // padded row (elems) -> conflict-free ldsm
#define TILE_B (128 * LDA * 2)       // 10240 bytes per (matrix,half) tile
#define STAGE_B (4 * TILE_B)         // Ah|Al|Bh|Bl = 40960
#define GEMM_SMEM (2 * STAGE_B)      // 81920

__global__ __launch_bounds__(256, 2) void qkv_gemm_hmma_kernel(
    const float* __restrict__ bias)
{
    extern __shared__ char smem[];
    const uint32_t smem_base = smem_to_u32(smem);

    const int tid = threadIdx.x;
    const int lane = tid & 31;
    const int w = tid >> 5;
    const int m0 = blockIdx.y * GBM;
    const int n0 = blockIdx.x * GBN;
    const int m_w = (w >> 2) * 64;     // warp tile origin in CTA
    const int n_w = (w & 3) * 32;

    // cp.async source bases (4 tiles: Ah, Al, Bh, Bl)
    const __nv_bfloat16* srcs[4] = {
        g_Ah + (size_t)m0 * 1024, g_Al + (size_t)m0 * 1024,
        g_Bh + (size_t)n0 * 1024, g_Bl + (size_t)n0 * 1024 };

    // ldmatrix per-thread offsets (bytes, within a stage)
    uint32_t aoff[4], boff[2];
#pragma unroll
    for (int mf = 0; mf < 4; mf++)
        aoff[mf] = ((m_w + mf * 16 + (lane & 15)) * LDA + (lane >> 4) * 8) * 2;
#pragma unroll
    for (int p = 0; p < 2; p++)
        boff[p] = ((n_w + p * 16 + (lane & 7) + (lane >> 4) * 8) * LDA
                   + ((lane >> 3) & 1) * 8) * 2;

    float Cr[4][4][4];
#pragma unroll
    for (int mf = 0; mf < 4; mf++)
#pragma unroll
        for (int nf = 0; nf < 4; nf++)
#pragma unroll
            for (int r = 0; r < 4; r++) Cr[mf][nf][r] = 0.0f;

    // stage loader: 2048 16B cp.async ops / 256 threads = 8 per thread
    auto load_stage = [&](int k0, int s) {
        const uint32_t sb = smem_base + s * STAGE_B;
#pragma unroll
        for (int t = 0; t < 8; t++) {
            int i = tid + t * 256;
            int tile = i >> 9;            // 0..3
            int j = i & 511;
            int row = j >> 2;             // 0..127
            int q = j & 3;                // 16B chunk within 32-elem row
            const __nv_bfloat16* src = srcs[tile] + (size_t)row * 1024 + k0 + q * 8;
            uint32_t dst = sb + tile * TILE_B + (row * LDA + q * 8) * 2;
            CP_ASYNC16(dst, src);
        }
        CP_ASYNC_COMMIT();
    };

    load_stage(0, 0);

    for (int c = 0; c < 32; c++) {
        const int s = c & 1;
        CP_ASYNC_WAIT_ALL();
        __syncthreads();
        if (c + 1 < 32) load_stage((c + 1) * GBK, s ^ 1);

        const uint32_t sb = smem_base + s * STAGE_B;
#pragma unroll
        for (int kk = 0; kk < 2; kk++) {
            const uint32_t ko = kk * 32;   // 16 elems * 2B
            uint32_t ah[4][4], al[4][4], bb[4][2];

            // A-hi fragments (4 x m16k16)
#pragma unroll
            for (int mf = 0; mf < 4; mf++)
                LDSM_X4(ah[mf][0], ah[mf][1], ah[mf][2], ah[mf][3],
                        sb + 0 * TILE_B + aoff[mf] + ko);
            // B-hi fragments (4 x k16n8, via 2 x4)
#pragma unroll
            for (int p = 0; p < 2; p++) {
                uint32_t r0, r1, r2, r3;
                LDSM_X4(r0, r1, r2, r3, sb + 2 * TILE_B + boff[p] + ko);
                bb[2 * p][0] = r0; bb[2 * p][1] = r1;
                bb[2 * p + 1][0] = r2; bb[2 * p + 1][1] = r3;
            }
            // pass 1: Ah x Bh
#pragma unroll
            for (int mf = 0; mf < 4; mf++)
#pragma unroll
                for (int nf = 0; nf < 4; nf++)
                    MMA_BF16(Cr[mf][nf], ah[mf], bb[nf]);

            // pass 2: Al x Bh (Bh still resident)
#pragma unroll
            for (int mf = 0; mf < 4; mf++)
                LDSM_X4(al[mf][0], al[mf][1], al[mf][2], al[mf][3],
                        sb + 1 * TILE_B + aoff[mf] + ko);
#pragma unroll
            for (int mf = 0; mf < 4; mf++)
#pragma unroll
                for (int nf = 0; nf < 4; nf++)
                    MMA_BF16(Cr[mf][nf], al[mf], bb[nf]);

            // pass 3: Ah x Bl (overwrite B regs)
#pragma unroll
            for (int p = 0; p < 2; p++) {
                uint32_t r0, r1, r2, r3;
                LDSM_X4(r0, r1, r2, r3, sb + 3 * TILE_B + boff[p] + ko);
                bb[2 * p][0] = r0; bb[2 * p][1] = r1;
                bb[2 * p + 1][0] = r2; bb[2 * p + 1][1] = r3;
            }
#pragma unroll
            for (int mf = 0; mf < 4; mf++)
#pragma unroll
                for (int nf = 0; nf < 4; nf++)
                    MMA_BF16(Cr[mf][nf], ah[mf], bb[nf]);
        }
    }

    // Epilogue: bias + scatter into g_q/g_k/g_v ([B,H,S,HD]).
    // C frag (m16n8): c0,c1 -> (row, col), (row, col+1); c2,c3 -> row+8.
#pragma unroll
    for (int nf = 0; nf < 4; nf++) {
        const int col = n0 + n_w + nf * 8 + 2 * (lane & 3);     // even
        const float bn0 = __ldg(&bias[col]);
        const float bn1 = __ldg(&bias[col + 1]);
        const int h = col / 192;
        const int rr = col - h * 192;
        const int sel = rr >> 6;
        const int hd = rr & 63;
        float* dst = (sel == 0) ? g_q : (sel == 1) ? g_k : g_v;
#pragma unroll
        for (int mf = 0; mf < 4; mf++) {
            const int row0 = m0 + m_w + mf * 16 + (lane >> 2);
#pragma unroll
            for (int half = 0; half < 2; half++) {
                const int row = row0 + half * 8;
                const int bidx = row >> 10;
                const int srow = row & 1023;
                float2 v2;
                v2.x = Cr[mf][nf][half * 2 + 0] + bn0;
                v2.y = Cr[mf][nf][half * 2 + 1] + bn1;
                *(float2*)&dst[((((size_t)bidx * HH + h) << 10) + srow) * HDIM + hd] = v2;
            }
        }
    }
}

// ---------------------------------------------------------------------------
// Kernel: flash attention, fp32, online softmax (unchanged, verified).
// ---------------------------------------------------------------------------
#define ATTN_SMEM_BYTES (4 * 64 * 68 * 4)

__global__ __launch_bounds__(256) void attn_kernel(float* __restrict__ out)
{
    extern __shared__ float smemf[];
    float (*Qt)[68] = (float(*)[68])(smemf);
    float (*Kt)[68] = (float(*)[68])(smemf + 64 * 68);
    float (*Vs)[68] = (float(*)[68])(smemf + 2 * 64 * 68);
    float (*Ps)[68] = (float(*)[68])(smemf + 3 * 64 * 68);

    const int qt = blockIdx.x;
    const int h  = blockIdx.y;
    const int b  = blockIdx.z;

    const size_t head_off = (((size_t)b * HH + h) << 10) * HDIM;
    const float* qp    = g_q + head_off + (size_t)qt * 64 * HDIM;
    const float* kbase = g_k + head_off;
    const float* vbase = g_v + head_off;

    const int tid = threadIdx.x;
    const int tx = tid & 15;
    const int g  = tid >> 4;
    const int qr = g * 4;
    const int cc = tx * 4;

#pragma unroll
    for (int it = 0; it < 4; it++) {
        int idx = tid + it * 256;
        int row = idx >> 4;
        int col = (idx & 15) * 4;
        float4 va = *(const float4*)&qp[row * HDIM + col];
        Qt[col + 0][row] = va.x;
        Qt[col + 1][row] = va.y;
        Qt[col + 2][row] = va.z;
        Qt[col + 3][row] = va.w;
    }

    float m_i[4], l_i[4], o[4][4];
#pragma unroll
    for (int i = 0; i < 4; i++) {
        m_i[i] = -1e30f;
        l_i[i] = 0.0f;
#pragma unroll
        for (int j = 0; j < 4; j++) o[i][j] = 0.0f;
    }

    for (int kt = 0; kt < 16; kt++) {
        const float* kp = kbase + (size_t)kt * 64 * HDIM;
        const float* vp = vbase + (size_t)kt * 64 * HDIM;

        __syncthreads();
#pragma unroll
        for (int it = 0; it < 4; it++) {
            int idx = tid + it * 256;
            int row = idx >> 4;
            int col = (idx & 15) * 4;
            float4 vk = *(const float4*)&kp[row * HDIM + col];
            Kt[col + 0][row] = vk.x;
            Kt[col + 1][row] = vk.y;
            Kt[col + 2][row] = vk.z;
            Kt[col + 3][row] = vk.w;
            *(float4*)&Vs[row][col] = *(const float4*)&vp[row * HDIM + col];
        }
        __syncthreads();

        float s[4][4];
#pragma unroll
        for (int i = 0; i < 4; i++)
#pragma unroll
            for (int j = 0; j < 4; j++) s[i][j] = 0.0f;

#pragma unroll 16
        for (int d = 0; d < 64; d++) {
            float4 a4 = *(const float4*)&Qt[d][qr];
            float4 k4 = *(const float4*)&Kt[d][cc];
            float av[4] = {a4.x, a4.y, a4.z, a4.w};
            float kv[4] = {k4.x, k4.y, k4.z, k4.w};
#pragma unroll
            for (int i = 0; i < 4; i++)
#pragma unroll
                for (int j = 0; j < 4; j++)
                    s[i][j] = fmaf(av[i], kv[j], s[i][j]);
        }
#pragma unroll
        for (int i = 0; i < 4; i++)
#pragma unroll
            for (int j = 0; j < 4; j++) s[i][j] *= 0.125f;

#pragma unroll
        for (int i = 0; i < 4; i++) {
            float t = fmaxf(fmaxf(s[i][0], s[i][1]), fmaxf(s[i][2], s[i][3]));
            t = fmaxf(t, __shfl_xor_sync(0xffffffffu, t, 8));
            t = fmaxf(t, __shfl_xor_sync(0xffffffffu, t, 4));
            t = fmaxf(t, __shfl_xor_sync(0xffffffffu, t, 2));
            t = fmaxf(t, __shfl_xor_sync(0xffffffffu, t, 1));

            float mnew = fmaxf(m_i[i], t);
            float corr = __expf(m_i[i] - mnew);
            m_i[i] = mnew;

            float ps = 0.0f;
#pragma unroll
            for (int j = 0; j < 4; j++) {
                float p = __expf(s[i][j] - mnew);
                s[i][j] = p;
                ps += p;
            }
            ps += __shfl_xor_sync(0xffffffffu, ps, 8);
            ps += __shfl_xor_sync(0xffffffffu, ps, 4);
            ps += __shfl_xor_sync(0xffffffffu, ps, 2);
            ps += __shfl_xor_sync(0xffffffffu, ps, 1);

            l_i[i] = l_i[i] * corr + ps;
#pragma unroll
            for (int j = 0; j < 4; j++) o[i][j] *= corr;
        }

#pragma unroll
        for (int i = 0; i < 4; i++)
            *(float4*)&Ps[qr + i][cc] =
                make_float4(s[i][0], s[i][1], s[i][2], s[i][3]);
        __syncthreads();

#pragma unroll 16
        for (int j = 0; j < 64; j++) {
            float4 v4 = *(const float4*)&Vs[j][cc];
            float vv[4] = {v4.x, v4.y, v4.z, v4.w};
            float p0 = Ps[qr + 0][j];
            float p1 = Ps[qr + 1][j];
            float p2 = Ps[qr + 2][j];
            float p3 = Ps[qr + 3][j];
#pragma unroll
            for (int jd = 0; jd < 4; jd++) {
                o[0][jd] = fmaf(p0, vv[jd], o[0][jd]);
                o[1][jd] = fmaf(p1, vv[jd], o[1][jd]);
                o[2][jd] = fmaf(p2, vv[jd], o[2][jd]);
                o[3][jd] = fmaf(p3, vv[jd], o[3][jd]);
            }
        }
    }

#pragma unroll
    for (int i = 0; i < 4; i++) {
        float inv = 1.0f / l_i[i];
        int srow = qt * 64 + qr + i;
        float4 r = make_float4(o[i][0] * inv, o[i][1] * inv,
                               o[i][2] * inv, o[i][3] * inv);
        *(float4*)&out[((((size_t)b << 10) + srow) << 10) + h * HDIM + cc] = r;
    }
}

// ---------------------------------------------------------------------------
extern "C" void kernel_launch(void* const* d_in, const int* in_sizes, int n_in,
                              void* d_out, int out_size)
{
    (void)in_sizes; (void)n_in; (void)out_size;
    const float* x    = (const float*)d_in[0];
    const float* W    = (const float*)d_in[1];
    const float* bias = (const float*)d_in[2];
    float* out = (float*)d_out;

    cudaFuncSetAttribute(qkv_gemm_hmma_kernel,
                         cudaFuncAttributeMaxDynamicSharedMemorySize, GEMM_SMEM);
    cudaFuncSetAttribute(attn_kernel,
                         cudaFuncAttributeMaxDynamicSharedMemorySize, ATTN_SMEM_BYTES);

    __nv_bfloat16 *Ah, *Al, *Bh, *Bl;
    cudaGetSymbolAddress((void**)&Ah, g_Ah);
    cudaGetSymbolAddress((void**)&Al, g_Al);
    cudaGetSymbolAddress((void**)&Bh, g_Bh);
    cudaGetSymbolAddress((void**)&Bl, g_Bl);

    prep_x_kernel<<<4096, 256>>>(x, Ah, Al);
    prep_w_kernel<<<dim3(96, 32), 256>>>(W, Bh, Bl);

    dim3 ggrid(3072 / GBN, 4096 / GBM);     // (24, 32)
    qkv_gemm_hmma_kernel<<<ggrid, 256, GEMM_SMEM>>>(bias);

    dim3 agrid(SS / 64, HH, BB);            // (16, 16, 4)
    attn_kernel<<<agrid, 256, ATTN_SMEM_BYTES>>>(out);
}

// round 7
// speedup vs baseline: 3.6952x; 2.2850x over previous
#include <cuda_runtime.h>
#include <cuda_bf16.h>
#include <cuda_fp16.h>
#include <cstdint>
#include <cstddef>

// Problem constants
#define BB 4
#define SS 1024
#define DD 1024
#define HH 16
#define HDIM 64

// Scratch (no alloc allowed)
__device__ __half g_q16[(size_t)BB * HH * SS * HDIM];
__device__ __half g_k16[(size_t)BB * HH * SS * HDIM];
__device__ __half g_v16[(size_t)BB * HH * SS * HDIM];
__device__ __nv_bfloat16 g_Ah[(size_t)4096 * 1024];
__device__ __nv_bfloat16 g_Al[(size_t)4096 * 1024];
__device__ __nv_bfloat16 g_Bh[(size_t)3072 * 1024];   // W transposed: [n][k]
__device__ __nv_bfloat16 g_Bl[(size_t)3072 * 1024];

// ---------------------------------------------------------------------------
// Portable (compute_103-legal) tensor-core PTX: mma.sync + ldmatrix + cp.async
// ---------------------------------------------------------------------------
__device__ __forceinline__ uint32_t smem_to_u32(const void* p) {
    uint32_t a;
    asm("{ .reg .u64 t; cvta.to.shared.u64 t, %1; cvt.u32.u64 %0, t; }"
        : "=r"(a) : "l"(p));
    return a;
}

#define CP_ASYNC16(dst_u32, src_ptr) \
    asm volatile("cp.async.cg.shared.global [%0], [%1], 16;" \
        :: "r"(dst_u32), "l"(src_ptr) : "memory")
#define CP_ASYNC_COMMIT() asm volatile("cp.async.commit_group;" ::: "memory")
#define CP_ASYNC_WAIT(n) asm volatile("cp.async.wait_group %0;" :: "n"(n) : "memory")

#define LDSM_X4(r0, r1, r2, r3, addr) \
    asm volatile("ldmatrix.sync.aligned.m8n8.x4.shared.b16 {%0,%1,%2,%3}, [%4];" \
        : "=r"(r0), "=r"(r1), "=r"(r2), "=r"(r3) : "r"(addr))
#define LDSM_X4_T(r0, r1, r2, r3, addr) \
    asm volatile("ldmatrix.sync.aligned.m8n8.x4.trans.shared.b16 {%0,%1,%2,%3}, [%4];" \
        : "=r"(r0), "=r"(r1), "=r"(r2), "=r"(r3) : "r"(addr))

#define MMA_BF16(d, a, b) \
    asm volatile("mma.sync.aligned.m16n8k16.row.col.f32.bf16.bf16.f32 " \
        "{%0,%1,%2,%3}, {%4,%5,%6,%7}, {%8,%9}, {%0,%1,%2,%3};" \
        : "+f"((d)[0]), "+f"((d)[1]), "+f"((d)[2]), "+f"((d)[3]) \
        : "r"((a)[0]), "r"((a)[1]), "r"((a)[2]), "r"((a)[3]), \
          "r"((b)[0]), "r"((b)[1]))

#define MMA_F16(d, a, b0v, b1v) \
    asm volatile("mma.sync.aligned.m16n8k16.row.col.f32.f16.f16.f32 " \
        "{%0,%1,%2,%3}, {%4,%5,%6,%7}, {%8,%9}, {%0,%1,%2,%3};" \
        : "+f"((d)[0]), "+f"((d)[1]), "+f"((d)[2]), "+f"((d)[3]) \
        : "r"((a)[0]), "r"((a)[1]), "r"((a)[2]), "r"((a)[3]), \
          "r"(b0v), "r"(b1v))

// ---------------------------------------------------------------------------
// Prep kernel 1: x [4096,1024] fp32 -> Ah/Al bf16 hi/lo
// ---------------------------------------------------------------------------
__global__ __launch_bounds__(256) void prep_x_kernel(
    const float* __restrict__ x,
    __nv_bfloat16* __restrict__ Ah, __nv_bfloat16* __restrict__ Al)
{
    size_t i = ((size_t)blockIdx.x * 256 + threadIdx.x) * 4;
    float4 v = *(const float4*)(x + i);
    float vv[4] = {v.x, v.y, v.z, v.w};
    __nv_bfloat16 h[4], l[4];
#pragma unroll
    for (int j = 0; j < 4; j++) {
        h[j] = __float2bfloat16(vv[j]);
        l[j] = __float2bfloat16(vv[j] - __bfloat162float(h[j]));
    }
    *(__nv_bfloat162*)(Ah + i)     = __nv_bfloat162{h[0], h[1]};
    *(__nv_bfloat162*)(Ah + i + 2) = __nv_bfloat162{h[2], h[3]};
    *(__nv_bfloat162*)(Al + i)     = __nv_bfloat162{l[0], l[1]};
    *(__nv_bfloat162*)(Al + i + 2) = __nv_bfloat162{l[2], l[3]};
}

// ---------------------------------------------------------------------------
// Prep kernel 2: W [1024,3072] fp32 -> transposed Bh/Bl [3072,1024] bf16
// ---------------------------------------------------------------------------
__global__ __launch_bounds__(256) void prep_w_kernel(
    const float* __restrict__ W,
    __nv_bfloat16* __restrict__ Bh, __nv_bfloat16* __restrict__ Bl)
{
    __shared__ float t[32][33];
    int n0 = blockIdx.x * 32, k0 = blockIdx.y * 32;
    int tx = threadIdx.x & 31, ty = threadIdx.x >> 5;    // ty 0..7
#pragma unroll
    for (int i = 0; i < 4; i++) {
        int k = k0 + ty + i * 8;
        t[ty + i * 8][tx] = W[(size_t)k * 3072 + n0 + tx];
    }
    __syncthreads();
#pragma unroll
    for (int i = 0; i < 4; i++) {
        int n = n0 + ty + i * 8;
        float v = t[tx][ty + i * 8];
        __nv_bfloat16 h = __float2bfloat16(v);
        Bh[(size_t)n * 1024 + k0 + tx] = h;
        Bl[(size_t)n * 1024 + k0 + tx] = __float2bfloat16(v - __bfloat162float(h));
    }
}

// ---------------------------------------------------------------------------
// QKV GEMM on HMMA (mma.sync bf16, fp32 accum, hi/lo 3-pass split).
// Mainloop unchanged (validated).  Epilogue now writes fp16 q/k/v [B,H,S,64].
// ---------------------------------------------------------------------------
#define GBM 128
#define GBN 128
#define GBK 32
#define LDA 40
#define TILE_B (128 * LDA * 2)
#define STAGE_B (4 * TILE_B)
#define GEMM_SMEM (2 * STAGE_B)

__global__ __launch_bounds__(256, 2) void qkv_gemm_hmma_kernel(
    const float* __restrict__ bias)
{
    extern __shared__ char smem[];
    const uint32_t smem_base = smem_to_u32(smem);

    const int tid = threadIdx.x;
    const int lane = tid & 31;
    const int w = tid >> 5;
    const int m0 = blockIdx.y * GBM;
    const int n0 = blockIdx.x * GBN;
    const int m_w = (w >> 2) * 64;
    const int n_w = (w & 3) * 32;

    const __nv_bfloat16* srcs[4] = {
        g_Ah + (size_t)m0 * 1024, g_Al + (size_t)m0 * 1024,
        g_Bh + (size_t)n0 * 1024, g_Bl + (size_t)n0 * 1024 };

    uint32_t aoff[4], boff[2];
#pragma unroll
    for (int mf = 0; mf < 4; mf++)
        aoff[mf] = ((m_w + mf * 16 + (lane & 15)) * LDA + (lane >> 4) * 8) * 2;
#pragma unroll
    for (int p = 0; p < 2; p++)
        boff[p] = ((n_w + p * 16 + (lane & 7) + (lane >> 4) * 8) * LDA
                   + ((lane >> 3) & 1) * 8) * 2;

    float Cr[4][4][4];
#pragma unroll
    for (int mf = 0; mf < 4; mf++)
#pragma unroll
        for (int nf = 0; nf < 4; nf++)
#pragma unroll
            for (int r = 0; r < 4; r++) Cr[mf][nf][r] = 0.0f;

    auto load_stage = [&](int k0, int s) {
        const uint32_t sb = smem_base + s * STAGE_B;
#pragma unroll
        for (int t = 0; t < 8; t++) {
            int i = tid + t * 256;
            int tile = i >> 9;
            int j = i & 511;
            int row = j >> 2;
            int q = j & 3;
            const __nv_bfloat16* src = srcs[tile] + (size_t)row * 1024 + k0 + q * 8;
            uint32_t dst = sb + tile * TILE_B + (row * LDA + q * 8) * 2;
            CP_ASYNC16(dst, src);
        }
        CP_ASYNC_COMMIT();
    };

    load_stage(0, 0);

    for (int c = 0; c < 32; c++) {
        const int s = c & 1;
        CP_ASYNC_WAIT(0);
        __syncthreads();
        if (c + 1 < 32) load_stage((c + 1) * GBK, s ^ 1);

        const uint32_t sb = smem_base + s * STAGE_B;
#pragma unroll
        for (int kk = 0; kk < 2; kk++) {
            const uint32_t ko = kk * 32;
            uint32_t ah[4][4], al[4][4], bb[4][2];

#pragma unroll
            for (int mf = 0; mf < 4; mf++)
                LDSM_X4(ah[mf][0], ah[mf][1], ah[mf][2], ah[mf][3],
                        sb + 0 * TILE_B + aoff[mf] + ko);
#pragma unroll
            for (int p = 0; p < 2; p++) {
                uint32_t r0, r1, r2, r3;
                LDSM_X4(r0, r1, r2, r3, sb + 2 * TILE_B + boff[p] + ko);
                bb[2 * p][0] = r0; bb[2 * p][1] = r1;
                bb[2 * p + 1][0] = r2; bb[2 * p + 1][1] = r3;
            }
#pragma unroll
            for (int mf = 0; mf < 4; mf++)
#pragma unroll
                for (int nf = 0; nf < 4; nf++)
                    MMA_BF16(Cr[mf][nf], ah[mf], bb[nf]);

#pragma unroll
            for (int mf = 0; mf < 4; mf++)
                LDSM_X4(al[mf][0], al[mf][1], al[mf][2], al[mf][3],
                        sb + 1 * TILE_B + aoff[mf] + ko);
#pragma unroll
            for (int mf = 0; mf < 4; mf++)
#pragma unroll
                for (int nf = 0; nf < 4; nf++)
                    MMA_BF16(Cr[mf][nf], al[mf], bb[nf]);

#pragma unroll
            for (int p = 0; p < 2; p++) {
                uint32_t r0, r1, r2, r3;
                LDSM_X4(r0, r1, r2, r3, sb + 3 * TILE_B + boff[p] + ko);
                bb[2 * p][0] = r0; bb[2 * p][1] = r1;
                bb[2 * p + 1][0] = r2; bb[2 * p + 1][1] = r3;
            }
#pragma unroll
            for (int mf = 0; mf < 4; mf++)
#pragma unroll
                for (int nf = 0; nf < 4; nf++)
                    MMA_BF16(Cr[mf][nf], ah[mf], bb[nf]);
        }
    }

    // Epilogue: bias + fp16 scatter into g_q16/g_k16/g_v16 ([B,H,S,64]).
#pragma unroll
    for (int nf = 0; nf < 4; nf++) {
        const int col = n0 + n_w + nf * 8 + 2 * (lane & 3);     // even
        const float bn0 = __ldg(&bias[col]);
        const float bn1 = __ldg(&bias[col + 1]);
        const int h = col / 192;
        const int rr = col - h * 192;
        const int sel = rr >> 6;
        const int hd = rr & 63;
        __half* dst = (sel == 0) ? g_q16 : (sel == 1) ? g_k16 : g_v16;
#pragma unroll
        for (int mf = 0; mf < 4; mf++) {
            const int row0 = m0 + m_w + mf * 16 + (lane >> 2);
#pragma unroll
            for (int half = 0; half < 2; half++) {
                const int row = row0 + half * 8;
                const int bidx = row >> 10;
                const int srow = row & 1023;
                __half2 v2 = __floats2half2_rn(Cr[mf][nf][half * 2 + 0] + bn0,
                                               Cr[mf][nf][half * 2 + 1] + bn1);
                *(__half2*)&dst[((((size_t)bidx * HH + h) << 10) + srow) * HDIM + hd] = v2;
            }
        }
    }
}

// ---------------------------------------------------------------------------
// Flash attention on HMMA fp16.  CTA: 128 queries x one (b,h).
// 8 warps x m16.  Key tiles of 64, cp.async double-buffered K/V.
// Q in registers; K via ldmatrix ([key][d] = B [n][k]); V via ldmatrix.trans.
// Softmax fp32 (exp2, 1/8 scale folded); P -> f16 in registers = PV A-frag.
// ---------------------------------------------------------------------------
#define LDK 72                          // padded row stride (elems)
#define QS_BYTES (128 * LDK * 2)        // 18432
#define KV_BYTES (64 * LDK * 2)         // 9216
#define ATTN_SMEM (QS_BYTES + 4 * KV_BYTES)   // 55296
#define L2E8 0.1803368801111204f        // 0.125 * log2(e)

__global__ __launch_bounds__(256, 2) void attn_tc_kernel(float* __restrict__ out)
{
    extern __shared__ char smem[];
    const uint32_t sbase = smem_to_u32(smem);
    const uint32_t qsb = sbase;
    const uint32_t kb0 = sbase + QS_BYTES;
    const uint32_t vb0 = sbase + QS_BYTES + 2 * KV_BYTES;

    const int qt = blockIdx.x;          // 0..7  (128-query tile)
    const int h  = blockIdx.y;
    const int b  = blockIdx.z;
    const size_t head_off = (((size_t)b * HH + h) << 10) * HDIM;
    const __half* qg = g_q16 + head_off + (size_t)qt * 128 * HDIM;
    const __half* kg = g_k16 + head_off;
    const __half* vg = g_v16 + head_off;

    const int tid = threadIdx.x;
    const int lane = tid & 31;
    const int w = tid >> 5;
    const int qb = w * 16;              // warp's query row base (in tile)

    // ---- prologue: async-load Q tile (group 0), then K/V tile 0 (group 1)
#pragma unroll
    for (int t = 0; t < 4; t++) {
        int i = tid + t * 256;          // 0..1023
        int row = i >> 3, ch = i & 7;
        CP_ASYNC16(qsb + (row * LDK + ch * 8) * 2, qg + row * 64 + ch * 8);
    }
    CP_ASYNC_COMMIT();
    {
#pragma unroll
        for (int t = 0; t < 2; t++) {
            int i = tid + t * 256;      // 0..511
            int row = i >> 3, ch = i & 7;
            CP_ASYNC16(kb0 + (row * LDK + ch * 8) * 2, kg + row * 64 + ch * 8);
            CP_ASYNC16(vb0 + (row * LDK + ch * 8) * 2, vg + row * 64 + ch * 8);
        }
        CP_ASYNC_COMMIT();
    }
    CP_ASYNC_WAIT(1);                   // Q resident
    __syncthreads();

    // Q fragments: 4 d-chunks x 4 regs (held for whole kernel)
    uint32_t qf[4][4];
#pragma unroll
    for (int kk = 0; kk < 4; kk++)
        LDSM_X4(qf[kk][0], qf[kk][1], qf[kk][2], qf[kk][3],
                qsb + ((qb + (lane & 15)) * LDK + (lane >> 4) * 8 + 16 * kk) * 2);

    float m0r = -1e30f, m1r = -1e30f, l0 = 0.0f, l1 = 0.0f;
    float o[8][4];
#pragma unroll
    for (int nt = 0; nt < 8; nt++)
#pragma unroll
        for (int r = 0; r < 4; r++) o[nt][r] = 0.0f;

    for (int kt = 0; kt < 16; kt++) {
        const int buf = kt & 1;
        if (kt + 1 < 16) {
            const uint32_t kbn = kb0 + (buf ^ 1) * KV_BYTES;
            const uint32_t vbn = vb0 + (buf ^ 1) * KV_BYTES;
            const __half* kp = kg + (size_t)(kt + 1) * 64 * 64;
            const __half* vp = vg + (size_t)(kt + 1) * 64 * 64;
#pragma unroll
            for (int t = 0; t < 2; t++) {
                int i = tid + t * 256;
                int row = i >> 3, ch = i & 7;
                CP_ASYNC16(kbn + (row * LDK + ch * 8) * 2, kp + row * 64 + ch * 8);
                CP_ASYNC16(vbn + (row * LDK + ch * 8) * 2, vp + row * 64 + ch * 8);
            }
            CP_ASYNC_COMMIT();
            CP_ASYNC_WAIT(1);
        } else {
            CP_ASYNC_WAIT(0);
        }
        __syncthreads();                 // tile kt resident

        const uint32_t kb = kb0 + buf * KV_BYTES;
        const uint32_t vb = vb0 + buf * KV_BYTES;

        // ---- S = Q K^T  (8 key n-tiles x 4 d-chunks)
        float s[8][4];
#pragma unroll
        for (int nt = 0; nt < 8; nt++)
#pragma unroll
            for (int r = 0; r < 4; r++) s[nt][r] = 0.0f;

#pragma unroll
        for (int p = 0; p < 4; p++) {
            const uint32_t kro = (16 * p + (lane & 7) + (lane >> 4) * 8) * LDK
                               + ((lane >> 3) & 1) * 8;
#pragma unroll
            for (int kk = 0; kk < 4; kk++) {
                uint32_t r0, r1, r2, r3;
                LDSM_X4(r0, r1, r2, r3, kb + (kro + 16 * kk) * 2);
                MMA_F16(s[2 * p],     qf[kk], r0, r1);
                MMA_F16(s[2 * p + 1], qf[kk], r2, r3);
            }
        }

        // ---- online softmax (rows g = lane>>2 and g+8; quad shfl 1,2)
        float tm0 = -1e30f, tm1 = -1e30f;
#pragma unroll
        for (int nt = 0; nt < 8; nt++) {
            tm0 = fmaxf(tm0, fmaxf(s[nt][0], s[nt][1]));
            tm1 = fmaxf(tm1, fmaxf(s[nt][2], s[nt][3]));
        }
        tm0 = fmaxf(tm0, __shfl_xor_sync(0xffffffffu, tm0, 1));
        tm0 = fmaxf(tm0, __shfl_xor_sync(0xffffffffu, tm0, 2));
        tm1 = fmaxf(tm1, __shfl_xor_sync(0xffffffffu, tm1, 1));
        tm1 = fmaxf(tm1, __shfl_xor_sync(0xffffffffu, tm1, 2));

        const float mn0 = fmaxf(m0r, tm0);
        const float mn1 = fmaxf(m1r, tm1);
        const float c0 = exp2f((m0r - mn0) * L2E8);
        const float c1 = exp2f((m1r - mn1) * L2E8);
        m0r = mn0; m1r = mn1;

        float ps0 = 0.0f, ps1 = 0.0f;
#pragma unroll
        for (int nt = 0; nt < 8; nt++) {
            s[nt][0] = exp2f((s[nt][0] - mn0) * L2E8);
            s[nt][1] = exp2f((s[nt][1] - mn0) * L2E8);
            s[nt][2] = exp2f((s[nt][2] - mn1) * L2E8);
            s[nt][3] = exp2f((s[nt][3] - mn1) * L2E8);
            ps0 += s[nt][0] + s[nt][1];
            ps1 += s[nt][2] + s[nt][3];
        }
        ps0 += __shfl_xor_sync(0xffffffffu, ps0, 1);
        ps0 += __shfl_xor_sync(0xffffffffu, ps0, 2);
        ps1 += __shfl_xor_sync(0xffffffffu, ps1, 1);
        ps1 += __shfl_xor_sync(0xffffffffu, ps1, 2);
        l0 = l0 * c0 + ps0;
        l1 = l1 * c1 + ps1;
#pragma unroll
        for (int nt = 0; nt < 8; nt++) {
            o[nt][0] *= c0; o[nt][1] *= c0;
            o[nt][2] *= c1; o[nt][3] *= c1;
        }

        // ---- P -> fp16 A-fragments (key-chunks of 16 = tile pairs)
        uint32_t pa[4][4];
#pragma unroll
        for (int kk = 0; kk < 4; kk++) {
            pa[kk][0] = __half2_raw(__floats2half2_rn(s[2 * kk][0], s[2 * kk][1])).x |
                        ((uint32_t)__half2_raw(__floats2half2_rn(s[2 * kk][0], s[2 * kk][1])).y << 16);
            // (packed below properly)
        }
        // proper packing (avoid double conversion above being miscompiled):
#pragma unroll
        for (int kk = 0; kk < 4; kk++) {
            __half2 h0 = __floats2half2_rn(s[2 * kk][0], s[2 * kk][1]);
            __half2 h1 = __floats2half2_rn(s[2 * kk][2], s[2 * kk][3]);
            __half2 h2 = __floats2half2_rn(s[2 * kk + 1][0], s[2 * kk + 1][1]);
            __half2 h3 = __floats2half2_rn(s[2 * kk + 1][2], s[2 * kk + 1][3]);
            pa[kk][0] = *(uint32_t*)&h0;
            pa[kk][1] = *(uint32_t*)&h1;
            pa[kk][2] = *(uint32_t*)&h2;
            pa[kk][3] = *(uint32_t*)&h3;
        }

        // ---- O += P V   (V via ldmatrix.trans from [key][d])
#pragma unroll
        for (int pd = 0; pd < 4; pd++) {
#pragma unroll
            for (int kk = 0; kk < 4; kk++) {
                const uint32_t vro = (16 * kk + (lane & 7) + ((lane >> 3) & 1) * 8) * LDK
                                   + 16 * pd + (lane >> 4) * 8;
                uint32_t r0, r1, r2, r3;
                LDSM_X4_T(r0, r1, r2, r3, vb + vro * 2);
                MMA_F16(o[2 * pd],     pa[kk], r0, r1);
                MMA_F16(o[2 * pd + 1], pa[kk], r2, r3);
            }
        }
        __syncthreads();                 // all warps done with buf before overwrite
    }

    // ---- normalize + write out[b][s][h*64+d]
    const float inv0 = 1.0f / l0;
    const float inv1 = 1.0f / l1;
    const int row0 = qt * 128 + qb + (lane >> 2);
    const int dcol = h * HDIM + 2 * (lane & 3);
#pragma unroll
    for (int nt = 0; nt < 8; nt++) {
        float2 v0 = make_float2(o[nt][0] * inv0, o[nt][1] * inv0);
        float2 v1 = make_float2(o[nt][2] * inv1, o[nt][3] * inv1);
        *(float2*)&out[(((size_t)b << 10) + row0) * 1024 + dcol + 8 * nt] = v0;
        *(float2*)&out[(((size_t)b << 10) + row0 + 8) * 1024 + dcol + 8 * nt] = v1;
    }
}

// ---------------------------------------------------------------------------
extern "C" void kernel_launch(void* const* d_in, const int* in_sizes, int n_in,
                              void* d_out, int out_size)
{
    (void)in_sizes; (void)n_in; (void)out_size;
    const float* x    = (const float*)d_in[0];
    const float* W    = (const float*)d_in[1];
    const float* bias = (const float*)d_in[2];
    float* out = (float*)d_out;

    cudaFuncSetAttribute(qkv_gemm_hmma_kernel,
                         cudaFuncAttributeMaxDynamicSharedMemorySize, GEMM_SMEM);
    cudaFuncSetAttribute(attn_tc_kernel,
                         cudaFuncAttributeMaxDynamicSharedMemorySize, ATTN_SMEM);

    __nv_bfloat16 *Ah, *Al, *Bh, *Bl;
    cudaGetSymbolAddress((void**)&Ah, g_Ah);
    cudaGetSymbolAddress((void**)&Al, g_Al);
    cudaGetSymbolAddress((void**)&Bh, g_Bh);
    cudaGetSymbolAddress((void**)&Bl, g_Bl);

    prep_x_kernel<<<4096, 256>>>(x, Ah, Al);
    prep_w_kernel<<<dim3(96, 32), 256>>>(W, Bh, Bl);

    dim3 ggrid(3072 / GBN, 4096 / GBM);     // (24, 32)
    qkv_gemm_hmma_kernel<<<ggrid, 256, GEMM_SMEM>>>(bias);

    dim3 agrid(SS / 128, HH, BB);           // (8, 16, 4)
    attn_tc_kernel<<<agrid, 256, ATTN_SMEM>>>(out);
}

// round 8
// speedup vs baseline: 4.6938x; 1.2703x over previous
#include <cuda_runtime.h>
#include <cuda_fp16.h>
#include <cstdint>
#include <cstddef>

// Problem constants
#define BB 4
#define SS 1024
#define DD 1024
#define HH 16
#define HDIM 64

// Scratch (no alloc allowed)
__device__ __half g_q16[(size_t)BB * HH * SS * HDIM];
__device__ __half g_k16[(size_t)BB * HH * SS * HDIM];
__device__ __half g_v16[(size_t)BB * HH * SS * HDIM];
__device__ __half g_Ah[(size_t)4096 * 1024];          // x hi (fp16)
__device__ __half g_Al[(size_t)4096 * 1024];          // x lo (fp16 residual)
__device__ __half g_Bh[(size_t)3072 * 1024];          // W transposed [n][k], fp16

// ---------------------------------------------------------------------------
// Portable (compute_103-legal) tensor-core PTX: mma.sync + ldmatrix + cp.async
// ---------------------------------------------------------------------------
__device__ __forceinline__ uint32_t smem_to_u32(const void* p) {
    uint32_t a;
    asm("{ .reg .u64 t; cvta.to.shared.u64 t, %1; cvt.u32.u64 %0, t; }"
        : "=r"(a) : "l"(p));
    return a;
}

#define CP_ASYNC16(dst_u32, src_ptr) \
    asm volatile("cp.async.cg.shared.global [%0], [%1], 16;" \
        :: "r"(dst_u32), "l"(src_ptr) : "memory")
#define CP_ASYNC_COMMIT() asm volatile("cp.async.commit_group;" ::: "memory")
#define CP_ASYNC_WAIT(n) asm volatile("cp.async.wait_group %0;" :: "n"(n) : "memory")

#define LDSM_X4(r0, r1, r2, r3, addr) \
    asm volatile("ldmatrix.sync.aligned.m8n8.x4.shared.b16 {%0,%1,%2,%3}, [%4];" \
        : "=r"(r0), "=r"(r1), "=r"(r2), "=r"(r3) : "r"(addr))
#define LDSM_X4_T(r0, r1, r2, r3, addr) \
    asm volatile("ldmatrix.sync.aligned.m8n8.x4.trans.shared.b16 {%0,%1,%2,%3}, [%4];" \
        : "=r"(r0), "=r"(r1), "=r"(r2), "=r"(r3) : "r"(addr))

#define MMA_F16(d, a, b0v, b1v) \
    asm volatile("mma.sync.aligned.m16n8k16.row.col.f32.f16.f16.f32 " \
        "{%0,%1,%2,%3}, {%4,%5,%6,%7}, {%8,%9}, {%0,%1,%2,%3};" \
        : "+f"((d)[0]), "+f"((d)[1]), "+f"((d)[2]), "+f"((d)[3]) \
        : "r"((a)[0]), "r"((a)[1]), "r"((a)[2]), "r"((a)[3]), \
          "r"(b0v), "r"(b1v))

// ---------------------------------------------------------------------------
// Prep kernel 1: x [4096,1024] fp32 -> Ah/Al fp16 hi/lo
// ---------------------------------------------------------------------------
__global__ __launch_bounds__(256) void prep_x_kernel(
    const float* __restrict__ x,
    __half* __restrict__ Ah, __half* __restrict__ Al)
{
    size_t i = ((size_t)blockIdx.x * 256 + threadIdx.x) * 4;
    float4 v = *(const float4*)(x + i);
    float vv[4] = {v.x, v.y, v.z, v.w};
    __half h[4], l[4];
#pragma unroll
    for (int j = 0; j < 4; j++) {
        h[j] = __float2half_rn(vv[j]);
        l[j] = __float2half_rn(vv[j] - __half2float(h[j]));
    }
    *(__half2*)(Ah + i)     = __half2{h[0], h[1]};
    *(__half2*)(Ah + i + 2) = __half2{h[2], h[3]};
    *(__half2*)(Al + i)     = __half2{l[0], l[1]};
    *(__half2*)(Al + i + 2) = __half2{l[2], l[3]};
}

// ---------------------------------------------------------------------------
// Prep kernel 2: W [1024,3072] fp32 -> transposed Bh [3072,1024] fp16
// ---------------------------------------------------------------------------
__global__ __launch_bounds__(256) void prep_w_kernel(
    const float* __restrict__ W, __half* __restrict__ Bh)
{
    __shared__ float t[32][33];
    int n0 = blockIdx.x * 32, k0 = blockIdx.y * 32;
    int tx = threadIdx.x & 31, ty = threadIdx.x >> 5;    // ty 0..7
#pragma unroll
    for (int i = 0; i < 4; i++) {
        int k = k0 + ty + i * 8;
        t[ty + i * 8][tx] = W[(size_t)k * 3072 + n0 + tx];
    }
    __syncthreads();
#pragma unroll
    for (int i = 0; i < 4; i++) {
        int n = n0 + ty + i * 8;
        Bh[(size_t)n * 1024 + k0 + tx] = __float2half_rn(t[tx][ty + i * 8]);
    }
}

// ---------------------------------------------------------------------------
// QKV GEMM on HMMA (mma.sync fp16, fp32 accum, hi/lo 2-pass split).
// C[4096,3072] = x @ W + b.  CTA tile 128x128, BK=32, 8 warps @ 64x32,
// 3-stage cp.async pipeline.  Epilogue writes fp16 q/k/v [B,H,S,64].
// ---------------------------------------------------------------------------
#define GBM 128
#define GBN 128
#define GBK 32
#define LDA 40
#define TILE_B (128 * LDA * 2)         // 10240 bytes
#define STAGE_B (3 * TILE_B)           // Ah|Al|Bh = 30720
#define GEMM_SMEM (3 * STAGE_B)        // 92160 (3 stages)

__global__ __launch_bounds__(256, 2) void qkv_gemm_hmma_kernel(
    const float* __restrict__ bias)
{
    extern __shared__ char smem[];
    const uint32_t smem_base = smem_to_u32(smem);

    const int tid = threadIdx.x;
    const int lane = tid & 31;
    const int w = tid >> 5;
    const int m0 = blockIdx.y * GBM;
    const int n0 = blockIdx.x * GBN;
    const int m_w = (w >> 2) * 64;
    const int n_w = (w & 3) * 32;

    const __half* srcs[3] = {
        g_Ah + (size_t)m0 * 1024, g_Al + (size_t)m0 * 1024,
        g_Bh + (size_t)n0 * 1024 };

    uint32_t aoff[4], boff[2];
#pragma unroll
    for (int mf = 0; mf < 4; mf++)
        aoff[mf] = ((m_w + mf * 16 + (lane & 15)) * LDA + (lane >> 4) * 8) * 2;
#pragma unroll
    for (int p = 0; p < 2; p++)
        boff[p] = ((n_w + p * 16 + (lane & 7) + (lane >> 4) * 8) * LDA
                   + ((lane >> 3) & 1) * 8) * 2;

    float Cr[4][4][4];
#pragma unroll
    for (int mf = 0; mf < 4; mf++)
#pragma unroll
        for (int nf = 0; nf < 4; nf++)
#pragma unroll
            for (int r = 0; r < 4; r++) Cr[mf][nf][r] = 0.0f;

    // stage loader: 1536 16B cp.async ops / 256 threads = 6 per thread
    auto load_stage = [&](int k0, int s) {
        const uint32_t sb = smem_base + s * STAGE_B;
#pragma unroll
        for (int t = 0; t < 6; t++) {
            int i = tid + t * 256;
            int tile = i >> 9;            // 0..2
            int j = i & 511;
            int row = j >> 2;             // 0..127
            int q = j & 3;
            const __half* src = srcs[tile] + (size_t)row * 1024 + k0 + q * 8;
            uint32_t dst = sb + tile * TILE_B + (row * LDA + q * 8) * 2;
            CP_ASYNC16(dst, src);
        }
        CP_ASYNC_COMMIT();
    };

    load_stage(0, 0);
    load_stage(GBK, 1);

    for (int c = 0; c < 32; c++) {
        const int s = c % 3;
        if (c < 31) { CP_ASYNC_WAIT(1); } else { CP_ASYNC_WAIT(0); }
        __syncthreads();
        if (c + 2 < 32) load_stage((c + 2) * GBK, (c + 2) % 3);

        const uint32_t sb = smem_base + s * STAGE_B;
#pragma unroll
        for (int kk = 0; kk < 2; kk++) {
            const uint32_t ko = kk * 32;   // 16 elems * 2B
            uint32_t ah[4][4], al[4][4], bb[4][2];

            // B fragments (4 x k16n8, via 2 x4)
#pragma unroll
            for (int p = 0; p < 2; p++) {
                uint32_t r0, r1, r2, r3;
                LDSM_X4(r0, r1, r2, r3, sb + 2 * TILE_B + boff[p] + ko);
                bb[2 * p][0] = r0; bb[2 * p][1] = r1;
                bb[2 * p + 1][0] = r2; bb[2 * p + 1][1] = r3;
            }
            // pass 1: Ah x Bh
#pragma unroll
            for (int mf = 0; mf < 4; mf++)
                LDSM_X4(ah[mf][0], ah[mf][1], ah[mf][2], ah[mf][3],
                        sb + 0 * TILE_B + aoff[mf] + ko);
#pragma unroll
            for (int mf = 0; mf < 4; mf++)
#pragma unroll
                for (int nf = 0; nf < 4; nf++)
                    MMA_F16(Cr[mf][nf], ah[mf], bb[nf][0], bb[nf][1]);

            // pass 2: Al x Bh
#pragma unroll
            for (int mf = 0; mf < 4; mf++)
                LDSM_X4(al[mf][0], al[mf][1], al[mf][2], al[mf][3],
                        sb + 1 * TILE_B + aoff[mf] + ko);
#pragma unroll
            for (int mf = 0; mf < 4; mf++)
#pragma unroll
                for (int nf = 0; nf < 4; nf++)
                    MMA_F16(Cr[mf][nf], al[mf], bb[nf][0], bb[nf][1]);
        }
    }

    // Epilogue: bias + fp16 scatter into g_q16/g_k16/g_v16 ([B,H,S,64]).
#pragma unroll
    for (int nf = 0; nf < 4; nf++) {
        const int col = n0 + n_w + nf * 8 + 2 * (lane & 3);     // even
        const float bn0 = __ldg(&bias[col]);
        const float bn1 = __ldg(&bias[col + 1]);
        const int h = col / 192;
        const int rr = col - h * 192;
        const int sel = rr >> 6;
        const int hd = rr & 63;
        __half* dst = (sel == 0) ? g_q16 : (sel == 1) ? g_k16 : g_v16;
#pragma unroll
        for (int mf = 0; mf < 4; mf++) {
            const int row0 = m0 + m_w + mf * 16 + (lane >> 2);
#pragma unroll
            for (int half = 0; half < 2; half++) {
                const int row = row0 + half * 8;
                const int bidx = row >> 10;
                const int srow = row & 1023;
                __half2 v2 = __floats2half2_rn(Cr[mf][nf][half * 2 + 0] + bn0,
                                               Cr[mf][nf][half * 2 + 1] + bn1);
                *(__half2*)&dst[((((size_t)bidx * HH + h) << 10) + srow) * HDIM + hd] = v2;
            }
        }
    }
}

// ---------------------------------------------------------------------------
// Flash attention on HMMA fp16 (validated in R7, unchanged semantics).
// CTA: 128 queries x one (b,h).  8 warps x m16 rows, key tiles of 64,
// double-buffered K/V via cp.async.  Softmax fp32 (exp2, 1/8 scale folded).
// ---------------------------------------------------------------------------
#define LDK 72
#define QS_BYTES (128 * LDK * 2)
#define KV_BYTES (64 * LDK * 2)
#define ATTN_SMEM (QS_BYTES + 4 * KV_BYTES)
#define L2E8 0.1803368801111204f        // 0.125 * log2(e)

__global__ __launch_bounds__(256, 2) void attn_tc_kernel(float* __restrict__ out)
{
    extern __shared__ char smem[];
    const uint32_t sbase = smem_to_u32(smem);
    const uint32_t qsb = sbase;
    const uint32_t kb0 = sbase + QS_BYTES;
    const uint32_t vb0 = sbase + QS_BYTES + 2 * KV_BYTES;

    const int qt = blockIdx.x;
    const int h  = blockIdx.y;
    const int b  = blockIdx.z;
    const size_t head_off = (((size_t)b * HH + h) << 10) * HDIM;
    const __half* qg = g_q16 + head_off + (size_t)qt * 128 * HDIM;
    const __half* kg = g_k16 + head_off;
    const __half* vg = g_v16 + head_off;

    const int tid = threadIdx.x;
    const int lane = tid & 31;
    const int w = tid >> 5;
    const int qb = w * 16;

#pragma unroll
    for (int t = 0; t < 4; t++) {
        int i = tid + t * 256;
        int row = i >> 3, ch = i & 7;
        CP_ASYNC16(qsb + (row * LDK + ch * 8) * 2, qg + row * 64 + ch * 8);
    }
    CP_ASYNC_COMMIT();
    {
#pragma unroll
        for (int t = 0; t < 2; t++) {
            int i = tid + t * 256;
            int row = i >> 3, ch = i & 7;
            CP_ASYNC16(kb0 + (row * LDK + ch * 8) * 2, kg + row * 64 + ch * 8);
            CP_ASYNC16(vb0 + (row * LDK + ch * 8) * 2, vg + row * 64 + ch * 8);
        }
        CP_ASYNC_COMMIT();
    }
    CP_ASYNC_WAIT(1);
    __syncthreads();

    uint32_t qf[4][4];
#pragma unroll
    for (int kk = 0; kk < 4; kk++)
        LDSM_X4(qf[kk][0], qf[kk][1], qf[kk][2], qf[kk][3],
                qsb + ((qb + (lane & 15)) * LDK + (lane >> 4) * 8 + 16 * kk) * 2);

    float m0r = -1e30f, m1r = -1e30f, l0 = 0.0f, l1 = 0.0f;
    float o[8][4];
#pragma unroll
    for (int nt = 0; nt < 8; nt++)
#pragma unroll
        for (int r = 0; r < 4; r++) o[nt][r] = 0.0f;

    for (int kt = 0; kt < 16; kt++) {
        const int buf = kt & 1;
        if (kt + 1 < 16) {
            const uint32_t kbn = kb0 + (buf ^ 1) * KV_BYTES;
            const uint32_t vbn = vb0 + (buf ^ 1) * KV_BYTES;
            const __half* kp = kg + (size_t)(kt + 1) * 64 * 64;
            const __half* vp = vg + (size_t)(kt + 1) * 64 * 64;
#pragma unroll
            for (int t = 0; t < 2; t++) {
                int i = tid + t * 256;
                int row = i >> 3, ch = i & 7;
                CP_ASYNC16(kbn + (row * LDK + ch * 8) * 2, kp + row * 64 + ch * 8);
                CP_ASYNC16(vbn + (row * LDK + ch * 8) * 2, vp + row * 64 + ch * 8);
            }
            CP_ASYNC_COMMIT();
            CP_ASYNC_WAIT(1);
        } else {
            CP_ASYNC_WAIT(0);
        }
        __syncthreads();

        const uint32_t kb = kb0 + buf * KV_BYTES;
        const uint32_t vb = vb0 + buf * KV_BYTES;

        float s[8][4];
#pragma unroll
        for (int nt = 0; nt < 8; nt++)
#pragma unroll
            for (int r = 0; r < 4; r++) s[nt][r] = 0.0f;

#pragma unroll
        for (int p = 0; p < 4; p++) {
            const uint32_t kro = (16 * p + (lane & 7) + (lane >> 4) * 8) * LDK
                               + ((lane >> 3) & 1) * 8;
#pragma unroll
            for (int kk = 0; kk < 4; kk++) {
                uint32_t r0, r1, r2, r3;
                LDSM_X4(r0, r1, r2, r3, kb + (kro + 16 * kk) * 2);
                MMA_F16(s[2 * p],     qf[kk], r0, r1);
                MMA_F16(s[2 * p + 1], qf[kk], r2, r3);
            }
        }

        float tm0 = -1e30f, tm1 = -1e30f;
#pragma unroll
        for (int nt = 0; nt < 8; nt++) {
            tm0 = fmaxf(tm0, fmaxf(s[nt][0], s[nt][1]));
            tm1 = fmaxf(tm1, fmaxf(s[nt][2], s[nt][3]));
        }
        tm0 = fmaxf(tm0, __shfl_xor_sync(0xffffffffu, tm0, 1));
        tm0 = fmaxf(tm0, __shfl_xor_sync(0xffffffffu, tm0, 2));
        tm1 = fmaxf(tm1, __shfl_xor_sync(0xffffffffu, tm1, 1));
        tm1 = fmaxf(tm1, __shfl_xor_sync(0xffffffffu, tm1, 2));

        const float mn0 = fmaxf(m0r, tm0);
        const float mn1 = fmaxf(m1r, tm1);
        const float c0 = exp2f((m0r - mn0) * L2E8);
        const float c1 = exp2f((m1r - mn1) * L2E8);
        m0r = mn0; m1r = mn1;

        float ps0 = 0.0f, ps1 = 0.0f;
#pragma unroll
        for (int nt = 0; nt < 8; nt++) {
            s[nt][0] = exp2f((s[nt][0] - mn0) * L2E8);
            s[nt][1] = exp2f((s[nt][1] - mn0) * L2E8);
            s[nt][2] = exp2f((s[nt][2] - mn1) * L2E8);
            s[nt][3] = exp2f((s[nt][3] - mn1) * L2E8);
            ps0 += s[nt][0] + s[nt][1];
            ps1 += s[nt][2] + s[nt][3];
        }
        ps0 += __shfl_xor_sync(0xffffffffu, ps0, 1);
        ps0 += __shfl_xor_sync(0xffffffffu, ps0, 2);
        ps1 += __shfl_xor_sync(0xffffffffu, ps1, 1);
        ps1 += __shfl_xor_sync(0xffffffffu, ps1, 2);
        l0 = l0 * c0 + ps0;
        l1 = l1 * c1 + ps1;
#pragma unroll
        for (int nt = 0; nt < 8; nt++) {
            o[nt][0] *= c0; o[nt][1] *= c0;
            o[nt][2] *= c1; o[nt][3] *= c1;
        }

        uint32_t pa[4][4];
#pragma unroll
        for (int kk = 0; kk < 4; kk++) {
            __half2 h0 = __floats2half2_rn(s[2 * kk][0], s[2 * kk][1]);
            __half2 h1 = __floats2half2_rn(s[2 * kk][2], s[2 * kk][3]);
            __half2 h2 = __floats2half2_rn(s[2 * kk + 1][0], s[2 * kk + 1][1]);
            __half2 h3 = __floats2half2_rn(s[2 * kk + 1][2], s[2 * kk + 1][3]);
            pa[kk][0] = *(uint32_t*)&h0;
            pa[kk][1] = *(uint32_t*)&h1;
            pa[kk][2] = *(uint32_t*)&h2;
            pa[kk][3] = *(uint32_t*)&h3;
        }

#pragma unroll
        for (int pd = 0; pd < 4; pd++) {
#pragma unroll
            for (int kk = 0; kk < 4; kk++) {
                const uint32_t vro = (16 * kk + (lane & 7) + ((lane >> 3) & 1) * 8) * LDK
                                   + 16 * pd + (lane >> 4) * 8;
                uint32_t r0, r1, r2, r3;
                LDSM_X4_T(r0, r1, r2, r3, vb + vro * 2);
                MMA_F16(o[2 * pd],     pa[kk], r0, r1);
                MMA_F16(o[2 * pd + 1], pa[kk], r2, r3);
            }
        }
        __syncthreads();
    }

    const float inv0 = 1.0f / l0;
    const float inv1 = 1.0f / l1;
    const int row0 = qt * 128 + qb + (lane >> 2);
    const int dcol = h * HDIM + 2 * (lane & 3);
#pragma unroll
    for (int nt = 0; nt < 8; nt++) {
        float2 v0 = make_float2(o[nt][0] * inv0, o[nt][1] * inv0);
        float2 v1 = make_float2(o[nt][2] * inv1, o[nt][3] * inv1);
        *(float2*)&out[(((size_t)b << 10) + row0) * 1024 + dcol + 8 * nt] = v0;
        *(float2*)&out[(((size_t)b << 10) + row0 + 8) * 1024 + dcol + 8 * nt] = v1;
    }
}

// ---------------------------------------------------------------------------
extern "C" void kernel_launch(void* const* d_in, const int* in_sizes, int n_in,
                              void* d_out, int out_size)
{
    (void)in_sizes; (void)n_in; (void)out_size;
    const float* x    = (const float*)d_in[0];
    const float* W    = (const float*)d_in[1];
    const float* bias = (const float*)d_in[2];
    float* out = (float*)d_out;

    cudaFuncSetAttribute(qkv_gemm_hmma_kernel,
                         cudaFuncAttributeMaxDynamicSharedMemorySize, GEMM_SMEM);
    cudaFuncSetAttribute(attn_tc_kernel,
                         cudaFuncAttributeMaxDynamicSharedMemorySize, ATTN_SMEM);

    __half *Ah, *Al, *Bh;
    cudaGetSymbolAddress((void**)&Ah, g_Ah);
    cudaGetSymbolAddress((void**)&Al, g_Al);
    cudaGetSymbolAddress((void**)&Bh, g_Bh);

    prep_x_kernel<<<4096, 256>>>(x, Ah, Al);
    prep_w_kernel<<<dim3(96, 32), 256>>>(W, Bh);

    dim3 ggrid(3072 / GBN, 4096 / GBM);     // (24, 32)
    qkv_gemm_hmma_kernel<<<ggrid, 256, GEMM_SMEM>>>(bias);

    dim3 agrid(SS / 128, HH, BB);           // (8, 16, 4)
    attn_tc_kernel<<<agrid, 256, ATTN_SMEM>>>(out);
}